// round 5
// baseline (speedup 1.0000x reference)
#include <cuda_runtime.h>
#include <cstdint>
#include <math_constants.h>

#define FULL 0xFFFFFFFFu

__device__ double g_batch_loss[256];

// Order-preserving bijection double -> uint64 (finite, no NaN).
__device__ __forceinline__ unsigned long long enc_key(double d) {
    long long b = __double_as_longlong(d);
    return (unsigned long long)(b ^ ((b >> 63) | 0x8000000000000000LL));
}
__device__ __forceinline__ double dec_key(unsigned long long k) {
    long long b = (k >> 63) ? (long long)(k ^ 0x8000000000000000ULL)
                            : ~(long long)k;
    return __longlong_as_double(b);
}

// Exact warp argmin over (key, idx), lowest idx wins ties.
// Fast path: REDUX on top-32 key bits + ballot; exact 5-level fallback.
__device__ __forceinline__ void warp_argmin(unsigned long long bk, int bi,
                                            unsigned long long& K, int& J) {
    unsigned hi = (unsigned)(bk >> 32);
    unsigned H  = __reduce_min_sync(FULL, hi);
    unsigned tied = __ballot_sync(FULL, hi == H);
    if (__popc(tied) == 1) {
        int wl = __ffs(tied) - 1;
        K = __shfl_sync(FULL, bk, wl);
        J = __shfl_sync(FULL, bi, wl);
    } else {
        unsigned long long xk = bk; int xi = bi;
        #pragma unroll
        for (int off = 16; off; off >>= 1) {
            unsigned long long ok = __shfl_xor_sync(FULL, xk, off);
            int oi = __shfl_xor_sync(FULL, xi, off);
            if (ok < xk || (ok == xk && oi < xi)) { xk = ok; xi = oi; }
        }
        K = xk; J = xi;
    }
}

// Exact warp min over 64-bit keys (value only).
__device__ __forceinline__ unsigned long long warp_minkey(unsigned long long bk) {
    unsigned hi = (unsigned)(bk >> 32);
    unsigned H  = __reduce_min_sync(FULL, hi);
    unsigned tied = __ballot_sync(FULL, hi == H);
    if (__popc(tied) == 1) {
        return __shfl_sync(FULL, bk, __ffs(tied) - 1);
    }
    unsigned long long xk = bk;
    #pragma unroll
    for (int off = 16; off; off >>= 1) {
        unsigned long long ok = __shfl_xor_sync(FULL, xk, off);
        if (ok < xk) xk = ok;
    }
    return xk;
}

// One warp per batch. Full JV: greedy row-min init + augmenting row reduction
// (with stealing) + shortest augmenting paths. Exact float64 LAP => identical
// optimal assignment to the numpy reference (unique optimum a.s.).
__global__ void __launch_bounds__(32) hungarian_kernel(
    const float* __restrict__ cost,   // [B, 64, 64]
    const float* __restrict__ gt,     // [B, 64, 2, 3]
    float* __restrict__ out)          // [B, 64] ordering (as float)
{
    const int b    = blockIdx.x;
    const int lane = threadIdx.x;

    __shared__ double cst[64][65];
    __shared__ double u_sh[64];
    __shared__ double minv_sh[64];
    __shared__ int    path_sh[64];
    __shared__ int    col4row[64];
    __shared__ int    row4col[64];
    __shared__ int    ord_sh[64];
    __shared__ int    colwin[64];

    // ---- load cost, convert to double ----
    const float* cb = cost + (size_t)b * 4096;
    for (int k = 0; k < 128; k++) {
        int idx = lane + 32 * k;
        cst[idx >> 6][idx & 63] = (double)cb[idx];
    }

    // ---- valid-count from gt_boxes ----
    const float* gb = gt + (size_t)b * 384;
    bool z_lo = true, z_hi = true;
    #pragma unroll
    for (int t = 0; t < 6; t++) {
        z_lo = z_lo && (gb[lane * 6 + t] == 0.0f);
        z_hi = z_hi && (gb[(lane + 32) * 6 + t] == 0.0f);
    }
    unsigned zb0 = __ballot_sync(FULL, z_lo);
    unsigned zb1 = __ballot_sync(FULL, z_hi);
    uint64_t zmask = (uint64_t)zb0 | ((uint64_t)zb1 << 32);
    const int c = zmask ? (__ffsll((long long)zmask) - 1) : 64;

    const int j0 = lane, j1 = lane + 32;
    const int r0 = lane, r1 = lane + 32;

    col4row[r0] = -1; col4row[r1] = -1;
    row4col[j0] = -1; row4col[j1] = -1;
    colwin[j0] = 127; colwin[j1] = 127;
    __syncwarp();

    // ---- row minima: u[i] = min_j cost[i][j] ----
    double um0 = CUDART_INF, um1 = CUDART_INF;
    int jm0 = 0, jm1 = 0;
    for (int j = 0; j < 64; j++) {
        double a0 = cst[r0][j];
        double a1 = cst[r1][j];
        if (a0 < um0) { um0 = a0; jm0 = j; }
        if (a1 < um1) { um1 = a1; jm1 = j; }
    }
    u_sh[r0] = um0; u_sh[r1] = um1;
    __syncwarp();

    // ---- greedy: each free argmin col to its lowest claiming row ----
    if (r0 < c) atomicMin(&colwin[jm0], r0);
    if (r1 < c) atomicMin(&colwin[jm1], r1);
    __syncwarp();
    if (r0 < c && colwin[jm0] == r0) { col4row[r0] = jm0; row4col[jm0] = r0; }
    if (r1 < c && colwin[jm1] == r1) { col4row[r1] = jm1; row4col[jm1] = r1; }
    __syncwarp();

    double v0 = 0.0, v1 = 0.0;
    const unsigned long long KINF = enc_key(CUDART_INF);
    const unsigned long long KMAX = ~0ull;

    // ---- augmenting row reduction with stealing (capped worklist) ----
    {
        unsigned f0 = __ballot_sync(FULL, r0 < c && col4row[r0] < 0);
        unsigned f1 = __ballot_sync(FULL, r1 < c && col4row[r1] < 0);
        uint64_t freemask = (uint64_t)f0 | ((uint64_t)f1 << 32);
        int cap = 2 * c;
        while (freemask && cap-- > 0) {
            const int i = __ffsll((long long)freemask) - 1;
            freemask &= freemask - 1;

            double d0 = cst[i][j0] - v0;
            double d1 = cst[i][j1] - v1;
            unsigned long long k0 = enc_key(d0), k1 = enc_key(d1);
            unsigned long long bk = k0; int bi = j0;
            if (k1 < bk) { bk = k1; bi = j1; }
            unsigned long long K1; int J1;
            warp_argmin(bk, bi, K1, J1);

            unsigned long long s0 = (j0 == J1) ? KMAX : k0;
            unsigned long long s1 = (j1 == J1) ? KMAX : k1;
            unsigned long long K2 = warp_minkey(s0 < s1 ? s0 : s1);

            double m1 = dec_key(K1), m2 = dec_key(K2);
            int kvic = row4col[J1];
            if (kvic < 0) {
                u_sh[i] = m1;
                col4row[i] = J1; row4col[J1] = i;
            } else {
                double dv = m2 - m1;
                if (j0 == J1) v0 -= dv;
                if (j1 == J1) v1 -= dv;
                u_sh[i] = m2;
                col4row[i] = J1; row4col[J1] = i;
                col4row[kvic] = -1;
                freemask |= 1ull << kvic;
            }
            __syncwarp();
        }
    }

    // ---- shortest augmenting path for each remaining free row ----
    for (int cur = 0; cur < c; cur++) {
        if (col4row[cur] >= 0) continue;   // uniform (shared state)

        unsigned long long mk0 = KINF, mk1 = KINF;
        int    path0 = -1, path1 = -1;
        uint64_t remaining = ~0ull;
        uint64_t SR = 0ull;
        int    i = cur;
        double ui = u_sh[cur];
        double min_val = 0.0;
        int    sink = -1;

        while (sink < 0) {
            SR |= (1ull << i);
            const double base = min_val - ui;
            const double* crow = cst[i];
            const bool rem0 = (remaining >> j0) & 1ull;
            const bool rem1 = (remaining >> j1) & 1ull;
            if (rem0) {
                double r = base + (crow[j0] - v0);
                unsigned long long rk = enc_key(r);
                if (rk < mk0) { mk0 = rk; path0 = i; }
            }
            if (rem1) {
                double r = base + (crow[j1] - v1);
                unsigned long long rk = enc_key(r);
                if (rk < mk1) { mk1 = rk; path1 = i; }
            }
            unsigned long long bk = rem0 ? mk0 : KMAX;
            int bi = j0;
            unsigned long long ck = rem1 ? mk1 : KMAX;
            if (ck < bk) { bk = ck; bi = j1; }

            // speculative next-row + next-u lookup (overlaps reduction)
            int    rc_loc = row4col[bi];
            double u_loc  = u_sh[rc_loc & 63];

            unsigned hi = (unsigned)(bk >> 32);
            unsigned H  = __reduce_min_sync(FULL, hi);
            unsigned tied = __ballot_sync(FULL, hi == H);

            unsigned long long K; int wbi; int wrc; double wu;
            if (__popc(tied) == 1) {
                int wl = __ffs(tied) - 1;
                K   = __shfl_sync(FULL, bk, wl);
                wbi = __shfl_sync(FULL, bi, wl);
                wrc = __shfl_sync(FULL, rc_loc, wl);
                wu  = __shfl_sync(FULL, u_loc, wl);
            } else {
                unsigned long long xk = bk; int xi = bi;
                #pragma unroll
                for (int off = 16; off; off >>= 1) {
                    unsigned long long ok = __shfl_xor_sync(FULL, xk, off);
                    int oi = __shfl_xor_sync(FULL, xi, off);
                    if (ok < xk || (ok == xk && oi < xi)) { xk = ok; xi = oi; }
                }
                K = xk; wbi = xi;
                wrc = row4col[wbi];
                wu  = u_sh[wrc & 63];
            }
            min_val = dec_key(K);
            remaining &= ~(1ull << wbi);
            if (wrc < 0) sink = wbi; else { i = wrc; ui = wu; }
        }

        double mv0 = dec_key(mk0), mv1 = dec_key(mk1);
        minv_sh[j0] = mv0; minv_sh[j1] = mv1;
        path_sh[j0] = path0; path_sh[j1] = path1;
        __syncwarp();

        // ---- dual updates ----
        if (lane == 0) u_sh[cur] += min_val;
        if (((SR >> r0) & 1ull) && r0 != cur) u_sh[r0] += min_val - minv_sh[col4row[r0]];
        if (((SR >> r1) & 1ull) && r1 != cur) u_sh[r1] += min_val - minv_sh[col4row[r1]];
        if (!((remaining >> j0) & 1ull)) v0 -= min_val - mv0;
        if (!((remaining >> j1) & 1ull)) v1 -= min_val - mv1;
        __syncwarp();

        // ---- augment ----
        int j = sink;
        while (true) {
            int i2 = path_sh[j];
            row4col[j] = i2;
            int t = col4row[i2];
            col4row[i2] = j;
            j = t;
            if (i2 == cur) break;
        }
        __syncwarp();
    }

    // ---- ordering: col4row[0:c] then unassigned columns ascending ----
    unsigned a0 = __ballot_sync(FULL, row4col[j0] >= 0);
    unsigned a1 = __ballot_sync(FULL, row4col[j1] >= 0);
    uint64_t used = (uint64_t)a0 | ((uint64_t)a1 << 32);
    ord_sh[j0] = (j0 < c) ? col4row[j0] : 0;
    ord_sh[j1] = (j1 < c) ? col4row[j1] : 0;
    __syncwarp();
    if (lane == 0) {
        int pos = c;
        uint64_t un = ~used;
        while (un) {
            int j = __ffsll((long long)un) - 1;
            un &= un - 1;
            ord_sh[pos++] = j;
        }
    }
    __syncwarp();

    float* ob = out + (size_t)b * 64;
    ob[j0] = (float)ord_sh[j0];
    ob[j1] = (float)ord_sh[j1];

    // ---- per-batch loss partial ----
    double ls = cst[j0][ord_sh[j0]] + cst[j1][ord_sh[j1]];
    #pragma unroll
    for (int off = 16; off; off >>= 1)
        ls += __shfl_xor_sync(FULL, ls, off);
    if (lane == 0) g_batch_loss[b] = ls;
}

__global__ void finalize_kernel(float* __restrict__ out, int out_elems, int bn)
{
    __shared__ double s[256];
    int t = threadIdx.x;
    s[t] = g_batch_loss[t];
    __syncthreads();
    for (int off = 128; off; off >>= 1) {
        if (t < off) s[t] += s[t + off];
        __syncthreads();
    }
    if (t == 0) {
        float loss = (float)(s[0] / (double)bn);
        for (int k = bn; k < out_elems; k++) out[k] = loss;
    }
}

extern "C" void kernel_launch(void* const* d_in, const int* in_sizes, int n_in,
                              void* d_out, int out_size)
{
    const float* cost = (const float*)d_in[0];
    const float* gt   = (const float*)d_in[1];
    float* out        = (float*)d_out;

    int B = in_sizes[0] / 4096;
    int bn = B * 64;

    hungarian_kernel<<<B, 32>>>(cost, gt, out);
    finalize_kernel<<<1, 256>>>(out, out_size, bn);
}

// round 6
// speedup vs baseline: 2.1286x; 2.1286x over previous
#include <cuda_runtime.h>
#include <cstdint>
#include <math_constants.h>

#define FULL 0xFFFFFFFFu

__device__ double g_batch_loss[256];

// Order-preserving bijection double -> uint64 (finite, no NaN).
__device__ __forceinline__ unsigned long long enc_key(double d) {
    long long b = __double_as_longlong(d);
    return (unsigned long long)(b ^ ((b >> 63) | 0x8000000000000000LL));
}
__device__ __forceinline__ double dec_key(unsigned long long k) {
    long long b = (k >> 63) ? (long long)(k ^ 0x8000000000000000ULL)
                            : ~(long long)k;
    return __longlong_as_double(b);
}

// One warp per batch. JV: greedy row-min init + warp-synchronous shortest
// augmenting paths with a fully branchless inner step (3xREDUX exact argmin).
// Exact float64 LAP => identical optimal assignment to the numpy reference.
__global__ void __launch_bounds__(32) hungarian_kernel(
    const float* __restrict__ cost,   // [B, 64, 64]
    const float* __restrict__ gt,     // [B, 64, 2, 3]
    float* __restrict__ out)          // [B, 64] ordering (as float)
{
    const int b    = blockIdx.x;
    const int lane = threadIdx.x;

    __shared__ double cst[64][65];
    __shared__ double u_sh[64];
    __shared__ double minv_sh[64];
    __shared__ int    path_sh[64];
    __shared__ int    col4row[64];
    __shared__ int    row4col[64];
    __shared__ int    ord_sh[64];
    __shared__ int    colwin[64];

    // ---- load cost (vectorized), convert to double ----
    {
        const float4* cb4 = (const float4*)(cost + (size_t)b * 4096);
        for (int k = 0; k < 32; k++) {
            int e = lane + 32 * k;            // float4 index: covers 4096 floats
            float4 f = cb4[e];
            int row = (e * 4) >> 6, col = (e * 4) & 63;
            cst[row][col + 0] = (double)f.x;
            cst[row][col + 1] = (double)f.y;
            cst[row][col + 2] = (double)f.z;
            cst[row][col + 3] = (double)f.w;
        }
    }

    // ---- valid-count from gt_boxes ----
    const float* gb = gt + (size_t)b * 384;
    bool z_lo = true, z_hi = true;
    #pragma unroll
    for (int t = 0; t < 6; t++) {
        z_lo = z_lo && (gb[lane * 6 + t] == 0.0f);
        z_hi = z_hi && (gb[(lane + 32) * 6 + t] == 0.0f);
    }
    unsigned zb0 = __ballot_sync(FULL, z_lo);
    unsigned zb1 = __ballot_sync(FULL, z_hi);
    uint64_t zmask = (uint64_t)zb0 | ((uint64_t)zb1 << 32);
    const int c = zmask ? (__ffsll((long long)zmask) - 1) : 64;

    const int j0 = lane, j1 = lane + 32;
    const int r0 = lane, r1 = lane + 32;

    col4row[r0] = -1; col4row[r1] = -1;
    row4col[j0] = -1; row4col[j1] = -1;
    colwin[j0] = 127; colwin[j1] = 127;
    __syncwarp();

    // ---- row minima: u[i] = min_j cost[i][j]; argmin col per row ----
    double um0 = CUDART_INF, um1 = CUDART_INF;
    int jm0 = 0, jm1 = 0;
    for (int j = 0; j < 64; j++) {
        double a0 = cst[r0][j];
        double a1 = cst[r1][j];
        if (a0 < um0) { um0 = a0; jm0 = j; }
        if (a1 < um1) { um1 = a1; jm1 = j; }
    }
    u_sh[r0] = um0; u_sh[r1] = um1;
    __syncwarp();

    // ---- greedy: each free argmin col to its lowest claiming row ----
    if (r0 < c) atomicMin(&colwin[jm0], r0);
    if (r1 < c) atomicMin(&colwin[jm1], r1);
    __syncwarp();
    if (r0 < c && colwin[jm0] == r0) { col4row[r0] = jm0; row4col[jm0] = r0; }
    if (r1 < c && colwin[jm1] == r1) { col4row[r1] = jm1; row4col[jm1] = r1; }
    __syncwarp();

    double v0 = 0.0, v1 = 0.0;
    const unsigned long long KINF = enc_key(CUDART_INF);
    const unsigned long long KMAX = ~0ull;

    // ---- shortest augmenting path for each remaining free row ----
    for (int cur = 0; cur < c; cur++) {
        if (col4row[cur] >= 0) continue;   // uniform

        unsigned long long mk0 = KINF, mk1 = KINF;
        int    path0 = -1, path1 = -1;
        uint64_t remaining = ~0ull;
        uint64_t SR = 0ull;
        int    i = cur;
        double ui = u_sh[cur];
        double min_val = 0.0;
        int    sink = -1;

        while (sink < 0) {
            SR |= (1ull << i);
            const double base = min_val - ui;
            const double* crow = cst[i];
            const bool rem0 = (remaining >> j0) & 1ull;
            const bool rem1 = (remaining >> j1) & 1ull;

            // branchless scan + min-update
            double rr0 = base + (crow[j0] - v0);
            double rr1 = base + (crow[j1] - v1);
            unsigned long long rk0 = enc_key(rr0);
            unsigned long long rk1 = enc_key(rr1);
            bool up0 = rem0 & (rk0 < mk0);
            bool up1 = rem1 & (rk1 < mk1);
            mk0 = up0 ? rk0 : mk0;  path0 = up0 ? i : path0;
            mk1 = up1 ? rk1 : mk1;  path1 = up1 ? i : path1;

            // local best (lower col wins ties)
            unsigned long long a0k = rem0 ? mk0 : KMAX;
            unsigned long long a1k = rem1 ? mk1 : KMAX;
            bool take1 = a1k < a0k;
            unsigned long long bk = take1 ? a1k : a0k;
            int bi = take1 ? j1 : j0;

            // speculative winner-state loads (overlap the reduction)
            int    rc_loc = row4col[bi];
            double u_loc  = u_sh[rc_loc & 63];

            // exact branchless argmin: 3-stage REDUX ladder
            unsigned hi = (unsigned)(bk >> 32);
            unsigned H  = __reduce_min_sync(FULL, hi);
            unsigned lo = (unsigned)bk;
            unsigned lo2 = (hi == H) ? lo : 0xFFFFFFFFu;
            unsigned L  = __reduce_min_sync(FULL, lo2);
            int bi2 = (hi == H && lo == L) ? bi : 127;
            int BI  = __reduce_min_sync(FULL, bi2);

            min_val = dec_key(((unsigned long long)H << 32) | L);
            int    wl  = BI & 31;            // bi values are lane-unique
            int    wrc = __shfl_sync(FULL, rc_loc, wl);
            double wu  = __shfl_sync(FULL, u_loc, wl);

            remaining &= ~(1ull << BI);
            bool fin = wrc < 0;
            sink = fin ? BI : -1;
            i    = fin ? i  : wrc;
            ui   = fin ? ui : wu;
        }

        // dump per-column state for cross-lane reads
        double mv0 = dec_key(mk0), mv1 = dec_key(mk1);
        minv_sh[j0] = mv0; minv_sh[j1] = mv1;
        path_sh[j0] = path0; path_sh[j1] = path1;
        __syncwarp();

        // ---- dual updates ----
        if (lane == 0) u_sh[cur] += min_val;
        if (((SR >> r0) & 1ull) && r0 != cur) u_sh[r0] += min_val - minv_sh[col4row[r0]];
        if (((SR >> r1) & 1ull) && r1 != cur) u_sh[r1] += min_val - minv_sh[col4row[r1]];
        if (!((remaining >> j0) & 1ull)) v0 -= min_val - mv0;
        if (!((remaining >> j1) & 1ull)) v1 -= min_val - mv1;
        __syncwarp();

        // ---- augment (all lanes redundantly, identical writes) ----
        int j = sink;
        while (true) {
            int i2 = path_sh[j];
            row4col[j] = i2;
            int t = col4row[i2];
            col4row[i2] = j;
            j = t;
            if (i2 == cur) break;
        }
        __syncwarp();
    }

    // ---- ordering: col4row[0:c] then unassigned columns ascending ----
    unsigned a0 = __ballot_sync(FULL, row4col[j0] >= 0);
    unsigned a1 = __ballot_sync(FULL, row4col[j1] >= 0);
    uint64_t used = (uint64_t)a0 | ((uint64_t)a1 << 32);
    ord_sh[j0] = (j0 < c) ? col4row[j0] : 0;
    ord_sh[j1] = (j1 < c) ? col4row[j1] : 0;
    __syncwarp();
    if (lane == 0) {
        int pos = c;
        uint64_t un = ~used;
        while (un) {
            int j = __ffsll((long long)un) - 1;
            un &= un - 1;
            ord_sh[pos++] = j;
        }
    }
    __syncwarp();

    float* ob = out + (size_t)b * 64;
    ob[j0] = (float)ord_sh[j0];
    ob[j1] = (float)ord_sh[j1];

    // ---- per-batch loss partial ----
    double ls = cst[j0][ord_sh[j0]] + cst[j1][ord_sh[j1]];
    #pragma unroll
    for (int off = 16; off; off >>= 1)
        ls += __shfl_xor_sync(FULL, ls, off);
    if (lane == 0) g_batch_loss[b] = ls;
}

__global__ void finalize_kernel(float* __restrict__ out, int out_elems, int bn)
{
    __shared__ double s[256];
    int t = threadIdx.x;
    s[t] = g_batch_loss[t];
    __syncthreads();
    for (int off = 128; off; off >>= 1) {
        if (t < off) s[t] += s[t + off];
        __syncthreads();
    }
    if (t == 0) {
        float loss = (float)(s[0] / (double)bn);
        for (int k = bn; k < out_elems; k++) out[k] = loss;
    }
}

extern "C" void kernel_launch(void* const* d_in, const int* in_sizes, int n_in,
                              void* d_out, int out_size)
{
    const float* cost = (const float*)d_in[0];
    const float* gt   = (const float*)d_in[1];
    float* out        = (float*)d_out;

    int B = in_sizes[0] / 4096;
    int bn = B * 64;

    hungarian_kernel<<<B, 32>>>(cost, gt, out);
    finalize_kernel<<<1, 256>>>(out, out_size, bn);
}